// round 1
// baseline (speedup 1.0000x reference)
#include <cuda_runtime.h>
#include <cstdint>
#include <cstddef>

#define S 1024
#define H 768
#define NHEADS 12
#define DH 64
#define BATCH 4
#define PROX 512
#define NEGV (-100000.0f)

// ---------------- scratch (allocation-free rule: device globals) ----------------
__device__ float g_q[(size_t)BATCH * S * H];
__device__ float g_k[(size_t)BATCH * S * H];
__device__ float g_v[(size_t)BATCH * S * H];

// =================================================================================
// Kernel 1: fused (x + masked vis) @ W^T + b  for Q/K/V.   grid = (6, 32, 3)
// Classic 128x128x8 fp32 SGEMM, 256 threads, 8x8 microtile.
// =================================================================================
__global__ void __launch_bounds__(256, 2) qkv_gemm(
    const float* __restrict__ hidden, const float* __restrict__ context,
    const float* __restrict__ vis, const int* __restrict__ feat_len,
    const float* __restrict__ Wq, const float* __restrict__ bq,
    const float* __restrict__ Wk, const float* __restrict__ bk,
    const float* __restrict__ Wv, const float* __restrict__ bv)
{
    const int z = blockIdx.z;
    const float* A = (z == 0) ? hidden : context;
    const float* W;
    const float* bias;
    float* C;
    if (z == 0)      { W = Wq; bias = bq; C = g_q; }
    else if (z == 1) { W = Wk; bias = bk; C = g_k; }
    else             { W = Wv; bias = bv; C = g_v; }

    const int m0 = blockIdx.y * 128;
    const int n0 = blockIdx.x * 128;
    const int b  = m0 >> 10;                 // 128-row tile never crosses a batch
    const int fl = feat_len[b];

    __shared__ float As[8][128];
    __shared__ float Bs[8][128];

    const int tid  = threadIdx.x;
    const int lrow = tid >> 1;               // 0..127
    const int lk   = (tid & 1) * 4;          // 0 or 4
    const bool addv = (((m0 + lrow) & (S - 1)) < fl);

    const float* Arow = A   + (size_t)(m0 + lrow) * H + lk;
    const float* Vrow = vis + (size_t)(m0 + lrow) * H + lk;
    const float* Wrow = W   + (size_t)(n0 + lrow) * H + lk;

    const int tx = tid & 15;
    const int ty = tid >> 4;

    float acc[8][8];
#pragma unroll
    for (int i = 0; i < 8; i++)
#pragma unroll
        for (int j = 0; j < 8; j++) acc[i][j] = 0.0f;

    for (int k0 = 0; k0 < H; k0 += 8) {
        float4 av = *(const float4*)(Arow + k0);
        if (addv) {
            float4 vv = *(const float4*)(Vrow + k0);
            av.x += vv.x; av.y += vv.y; av.z += vv.z; av.w += vv.w;
        }
        float4 wv = *(const float4*)(Wrow + k0);

        __syncthreads();
        As[lk + 0][lrow] = av.x; As[lk + 1][lrow] = av.y;
        As[lk + 2][lrow] = av.z; As[lk + 3][lrow] = av.w;
        Bs[lk + 0][lrow] = wv.x; Bs[lk + 1][lrow] = wv.y;
        Bs[lk + 2][lrow] = wv.z; Bs[lk + 3][lrow] = wv.w;
        __syncthreads();

#pragma unroll
        for (int kk = 0; kk < 8; kk++) {
            float4 a0 = *(const float4*)&As[kk][ty * 8];
            float4 a1 = *(const float4*)&As[kk][ty * 8 + 4];
            float4 b0 = *(const float4*)&Bs[kk][tx * 8];
            float4 b1 = *(const float4*)&Bs[kk][tx * 8 + 4];
            float a[8] = {a0.x, a0.y, a0.z, a0.w, a1.x, a1.y, a1.z, a1.w};
            float bb[8] = {b0.x, b0.y, b0.z, b0.w, b1.x, b1.y, b1.z, b1.w};
#pragma unroll
            for (int i = 0; i < 8; i++)
#pragma unroll
                for (int j = 0; j < 8; j++) acc[i][j] += a[i] * bb[j];
        }
    }

    float4 bi0 = *(const float4*)&bias[n0 + tx * 8];
    float4 bi1 = *(const float4*)&bias[n0 + tx * 8 + 4];
#pragma unroll
    for (int i = 0; i < 8; i++) {
        size_t off = (size_t)(m0 + ty * 8 + i) * H + n0 + tx * 8;
        float4 o0 = {acc[i][0] + bi0.x, acc[i][1] + bi0.y, acc[i][2] + bi0.z, acc[i][3] + bi0.w};
        float4 o1 = {acc[i][4] + bi1.x, acc[i][5] + bi1.y, acc[i][6] + bi1.z, acc[i][7] + bi1.w};
        *(float4*)&C[off]     = o0;
        *(float4*)&C[off + 4] = o1;
    }
}

// =================================================================================
// Kernel 2: fused attention per (b, h, 32-row q tile).   grid = (32, 12, 4)
// Phase A: scores = (QK^T/8)*gate + amask, custom mask  -> gmem scores + SMEM rows
// Phase B: warp-per-row softmax in SMEM
// Phase C: out = P @ V
// SMEM: Ps[32][1024] | Qt[64][36] | KV (Kt[64][260] / Vs[256][68]) = 209920 B
// =================================================================================
#define SM_PS   0
#define SM_QT   (32 * 1024)              // + 64*36  = 2304
#define SM_KV   (32 * 1024 + 64 * 36)    // + 17408
#define SM_FLOATS (32 * 1024 + 64 * 36 + 17408)
#define SMEM_BYTES (SM_FLOATS * 4)

__global__ void __launch_bounds__(256, 1) attn_kernel(
    const float* __restrict__ gate, const float* __restrict__ amask,
    const int* __restrict__ feat_len,
    float* __restrict__ out, float* __restrict__ scores_out)
{
    extern __shared__ float sm[];
    float* Ps = sm + SM_PS;
    float* Qt = sm + SM_QT;   // [64][36], transposed Q tile
    float* KV = sm + SM_KV;   // phase A: Kt[64][260]; phase C: Vs[256][68]

    const int qt = blockIdx.x;
    const int h  = blockIdx.y;
    const int b  = blockIdx.z;
    const int q0 = qt * 32;
    const int tid = threadIdx.x;
    const int flm1 = feat_len[b] - 1;

    // ---- load Q tile transposed: Qt[d][r] ----
#pragma unroll
    for (int it = 0; it < 2; it++) {
        int idx = tid + it * 256;          // 0..511
        int r   = idx >> 4;                // 0..31
        int d4  = (idx & 15) * 4;
        const float4 v = *(const float4*)&g_q[(size_t)(b * S + q0 + r) * H + h * DH + d4];
        Qt[(d4 + 0) * 36 + r] = v.x;
        Qt[(d4 + 1) * 36 + r] = v.y;
        Qt[(d4 + 2) * 36 + r] = v.z;
        Qt[(d4 + 3) * 36 + r] = v.w;
    }

    const int qg = tid >> 5;     // 0..7
    const int kg = tid & 31;     // 0..31
    const int qr = qg * 4;       // local q row base

    // ================= Phase A: scores =================
    for (int kt = 0; kt < S; kt += 256) {
        __syncthreads();  // prior users of KV done; also makes Qt visible on iter 0
        // load K tile transposed: Kt[d][r], r in [0,256)
#pragma unroll
        for (int it = 0; it < 16; it++) {
            int idx = tid + it * 256;
            int r   = idx >> 4;             // 0..255
            int d4  = (idx & 15) * 4;
            const float4 v = *(const float4*)&g_k[(size_t)(b * S + kt + r) * H + h * DH + d4];
            KV[(d4 + 0) * 260 + r] = v.x;
            KV[(d4 + 1) * 260 + r] = v.y;
            KV[(d4 + 2) * 260 + r] = v.z;
            KV[(d4 + 3) * 260 + r] = v.w;
        }
        __syncthreads();

        float acc[4][8];
#pragma unroll
        for (int i = 0; i < 4; i++)
#pragma unroll
            for (int j = 0; j < 8; j++) acc[i][j] = 0.0f;

#pragma unroll 16
        for (int d = 0; d < 64; d++) {
            float4 a4 = *(const float4*)&Qt[d * 36 + qr];
            float4 b0 = *(const float4*)&KV[d * 260 + kg * 8];
            float4 b1 = *(const float4*)&KV[d * 260 + kg * 8 + 4];
            float a[4] = {a4.x, a4.y, a4.z, a4.w};
            float bb[8] = {b0.x, b0.y, b0.z, b0.w, b1.x, b1.y, b1.z, b1.w};
#pragma unroll
            for (int i = 0; i < 4; i++)
#pragma unroll
                for (int j = 0; j < 8; j++) acc[i][j] += a[i] * bb[j];
        }

        // epilogue: scale, gate, mask; write scores + Ps
        const int kbase = kt + kg * 8;
        const float4 am0 = *(const float4*)&amask[b * S + kbase];
        const float4 am1 = *(const float4*)&amask[b * S + kbase + 4];
        const float am[8] = {am0.x, am0.y, am0.z, am0.w, am1.x, am1.y, am1.z, am1.w};
#pragma unroll
        for (int i = 0; i < 4; i++) {
            const int qrow = q0 + qr + i;
            const float4 g0 = *(const float4*)&gate[((size_t)b * S + qrow) * S + kbase];
            const float4 g1 = *(const float4*)&gate[((size_t)b * S + qrow) * S + kbase + 4];
            const float gg[8] = {g0.x, g0.y, g0.z, g0.w, g1.x, g1.y, g1.z, g1.w};
            float sc[8];
#pragma unroll
            for (int j = 0; j < 8; j++) {
                const int kc = kbase + j;
                float v = acc[i][j] * 0.125f * gg[j] + am[j];
                bool masked;
                if (qrow >= PROX) {
                    masked = (kc >= PROX) || (kc < flm1);
                } else if (qrow < PROX - 1) {
                    masked = (kc > qrow) || (kc < qrow - 1);
                } else {
                    masked = false;          // row 511: fully unmasked
                }
                sc[j] = masked ? NEGV : v;
            }
            float4 s0 = {sc[0], sc[1], sc[2], sc[3]};
            float4 s1 = {sc[4], sc[5], sc[6], sc[7]};
            *(float4*)&Ps[(qr + i) * S + kbase]     = s0;
            *(float4*)&Ps[(qr + i) * S + kbase + 4] = s1;
            size_t soff = ((size_t)(b * NHEADS + h) * S + qrow) * S + kbase;
            *(float4*)&scores_out[soff]     = s0;
            *(float4*)&scores_out[soff + 4] = s1;
        }
    }
    __syncthreads();

    // ================= Phase B: softmax (warp per row) =================
    {
        const int lane = tid & 31;
        const int w    = tid >> 5;
#pragma unroll
        for (int rr = 0; rr < 4; rr++) {
            float* row = Ps + (w * 4 + rr) * S;
            float m = -3.4e38f;
            for (int c = lane; c < S; c += 32) m = fmaxf(m, row[c]);
#pragma unroll
            for (int off = 16; off > 0; off >>= 1)
                m = fmaxf(m, __shfl_xor_sync(0xFFFFFFFFu, m, off));
            float ssum = 0.0f;
            for (int c = lane; c < S; c += 32) {
                float e = __expf(row[c] - m);
                row[c] = e;
                ssum += e;
            }
#pragma unroll
            for (int off = 16; off > 0; off >>= 1)
                ssum += __shfl_xor_sync(0xFFFFFFFFu, ssum, off);
            float inv = 1.0f / ssum;
            for (int c = lane; c < S; c += 32) row[c] *= inv;
        }
    }
    __syncthreads();

    // ================= Phase C: out = P @ V =================
    float oacc[4][2];
#pragma unroll
    for (int i = 0; i < 4; i++) { oacc[i][0] = 0.0f; oacc[i][1] = 0.0f; }

    for (int kt = 0; kt < S; kt += 256) {
        // load V tile natural layout: Vs[r][d], pitch 68
#pragma unroll
        for (int it = 0; it < 16; it++) {
            int idx = tid + it * 256;
            int r   = idx >> 4;
            int d4  = (idx & 15) * 4;
            *(float4*)&KV[r * 68 + d4] =
                *(const float4*)&g_v[(size_t)(b * S + kt + r) * H + h * DH + d4];
        }
        __syncthreads();

#pragma unroll 2
        for (int k = 0; k < 256; k += 4) {
            float4 p[4];
#pragma unroll
            for (int i = 0; i < 4; i++)
                p[i] = *(const float4*)&Ps[(qr + i) * S + kt + k];
#pragma unroll
            for (int j = 0; j < 4; j++) {
                float v0 = KV[(k + j) * 68 + kg];
                float v1 = KV[(k + j) * 68 + kg + 32];
                float pj[4] = { j == 0 ? p[0].x : j == 1 ? p[0].y : j == 2 ? p[0].z : p[0].w,
                                j == 0 ? p[1].x : j == 1 ? p[1].y : j == 2 ? p[1].z : p[1].w,
                                j == 0 ? p[2].x : j == 1 ? p[2].y : j == 2 ? p[2].z : p[2].w,
                                j == 0 ? p[3].x : j == 1 ? p[3].y : j == 2 ? p[3].z : p[3].w };
#pragma unroll
                for (int i = 0; i < 4; i++) {
                    oacc[i][0] += pj[i] * v0;
                    oacc[i][1] += pj[i] * v1;
                }
            }
        }
        __syncthreads();
    }

#pragma unroll
    for (int i = 0; i < 4; i++) {
        size_t ooff = (size_t)(b * S + q0 + qr + i) * H + h * DH;
        out[ooff + kg]      = oacc[i][0];
        out[ooff + kg + 32] = oacc[i][1];
    }
}

// =================================================================================
extern "C" void kernel_launch(void* const* d_in, const int* in_sizes, int n_in,
                              void* d_out, int out_size) {
    const float* hidden   = (const float*)d_in[0];
    const float* context  = (const float*)d_in[1];
    const float* amask    = (const float*)d_in[2];   // (B,1,1,S)
    const float* gate     = (const float*)d_in[3];   // (B,1,S,S)
    const float* vis      = (const float*)d_in[4];
    const float* Wq       = (const float*)d_in[5];
    const float* bq       = (const float*)d_in[6];
    const float* Wk       = (const float*)d_in[7];
    const float* bk       = (const float*)d_in[8];
    const float* Wv       = (const float*)d_in[9];
    const float* bv       = (const float*)d_in[10];
    const int*   feat_len = (const int*)d_in[11];
    // d_in[12] = prox_pos (constant 512, hardcoded)

    float* out_ptr = (float*)d_out;
    // tuple output: (out [B*S*H], scores [B*nH*S*S]) concatenated
    float* scores_ptr = out_ptr + (size_t)BATCH * S * H;

    qkv_gemm<<<dim3(6, 32, 3), 256>>>(hidden, context, vis, feat_len,
                                      Wq, bq, Wk, bk, Wv, bv);

    cudaFuncSetAttribute(attn_kernel, cudaFuncAttributeMaxDynamicSharedMemorySize,
                         SMEM_BYTES);
    attn_kernel<<<dim3(32, NHEADS, BATCH), 256, SMEM_BYTES>>>(
        gate, amask, feat_len, out_ptr, scores_ptr);
}

// round 2
// speedup vs baseline: 2.0814x; 2.0814x over previous
#include <cuda_runtime.h>
#include <cstdint>
#include <cstddef>

#define S 1024
#define H 768
#define NHEADS 12
#define DH 64
#define BATCH 4
#define PROX 512
#define NEGV (-100000.0f)

// ---------------- scratch (allocation-free rule: device globals) ----------------
__device__ float g_q[(size_t)BATCH * S * H];
__device__ float g_k[(size_t)BATCH * S * H];
__device__ float g_v[(size_t)BATCH * S * H];

// =================================================================================
// Kernel 1: fused (x + masked vis) @ W^T + b  for Q/K/V.   grid = (6, 32, 3)
// Classic 128x128x8 fp32 SGEMM, 256 threads, 8x8 microtile. (~fp32 FFMA ceiling)
// =================================================================================
__global__ void __launch_bounds__(256, 2) qkv_gemm(
    const float* __restrict__ hidden, const float* __restrict__ context,
    const float* __restrict__ vis, const int* __restrict__ feat_len,
    const float* __restrict__ Wq, const float* __restrict__ bq,
    const float* __restrict__ Wk, const float* __restrict__ bk,
    const float* __restrict__ Wv, const float* __restrict__ bv)
{
    const int z = blockIdx.z;
    const float* A = (z == 0) ? hidden : context;
    const float* W;
    const float* bias;
    float* C;
    if (z == 0)      { W = Wq; bias = bq; C = g_q; }
    else if (z == 1) { W = Wk; bias = bk; C = g_k; }
    else             { W = Wv; bias = bv; C = g_v; }

    const int m0 = blockIdx.y * 128;
    const int n0 = blockIdx.x * 128;
    const int b  = m0 >> 10;
    const int fl = feat_len[b];

    __shared__ float As[8][128];
    __shared__ float Bs[8][128];

    const int tid  = threadIdx.x;
    const int lrow = tid >> 1;
    const int lk   = (tid & 1) * 4;
    const bool addv = (((m0 + lrow) & (S - 1)) < fl);

    const float* Arow = A   + (size_t)(m0 + lrow) * H + lk;
    const float* Vrow = vis + (size_t)(m0 + lrow) * H + lk;
    const float* Wrow = W   + (size_t)(n0 + lrow) * H + lk;

    const int tx = tid & 15;
    const int ty = tid >> 4;

    float acc[8][8];
#pragma unroll
    for (int i = 0; i < 8; i++)
#pragma unroll
        for (int j = 0; j < 8; j++) acc[i][j] = 0.0f;

    for (int k0 = 0; k0 < H; k0 += 8) {
        float4 av = *(const float4*)(Arow + k0);
        if (addv) {
            float4 vv = *(const float4*)(Vrow + k0);
            av.x += vv.x; av.y += vv.y; av.z += vv.z; av.w += vv.w;
        }
        float4 wv = *(const float4*)(Wrow + k0);

        __syncthreads();
        As[lk + 0][lrow] = av.x; As[lk + 1][lrow] = av.y;
        As[lk + 2][lrow] = av.z; As[lk + 3][lrow] = av.w;
        Bs[lk + 0][lrow] = wv.x; Bs[lk + 1][lrow] = wv.y;
        Bs[lk + 2][lrow] = wv.z; Bs[lk + 3][lrow] = wv.w;
        __syncthreads();

#pragma unroll
        for (int kk = 0; kk < 8; kk++) {
            float4 a0 = *(const float4*)&As[kk][ty * 8];
            float4 a1 = *(const float4*)&As[kk][ty * 8 + 4];
            float4 b0 = *(const float4*)&Bs[kk][tx * 8];
            float4 b1 = *(const float4*)&Bs[kk][tx * 8 + 4];
            float a[8] = {a0.x, a0.y, a0.z, a0.w, a1.x, a1.y, a1.z, a1.w};
            float bb[8] = {b0.x, b0.y, b0.z, b0.w, b1.x, b1.y, b1.z, b1.w};
#pragma unroll
            for (int i = 0; i < 8; i++)
#pragma unroll
                for (int j = 0; j < 8; j++) acc[i][j] += a[i] * bb[j];
        }
    }

    float4 bi0 = *(const float4*)&bias[n0 + tx * 8];
    float4 bi1 = *(const float4*)&bias[n0 + tx * 8 + 4];
#pragma unroll
    for (int i = 0; i < 8; i++) {
        size_t off = (size_t)(m0 + ty * 8 + i) * H + n0 + tx * 8;
        float4 o0 = {acc[i][0] + bi0.x, acc[i][1] + bi0.y, acc[i][2] + bi0.z, acc[i][3] + bi0.w};
        float4 o1 = {acc[i][4] + bi1.x, acc[i][5] + bi1.y, acc[i][6] + bi1.z, acc[i][7] + bi1.w};
        *(float4*)&C[off]     = o0;
        *(float4*)&C[off + 4] = o1;
    }
}

// =================================================================================
// Kernel 2a: band rows r in [0, 511).  Only cols {r-1, r} survive the mask.
// One warp per (b,h,row). grid = (64, 12, 4), block = 256.
// =================================================================================
__global__ void __launch_bounds__(256) band_kernel(
    const float* __restrict__ gate, const float* __restrict__ amask,
    float* __restrict__ out, float* __restrict__ scores_out)
{
    const int lane = threadIdx.x & 31;
    const int w    = threadIdx.x >> 5;
    const int r    = blockIdx.x * 8 + w;
    if (r >= PROX - 1) return;             // rows 0..510
    const int h = blockIdx.y;
    const int b = blockIdx.z;

    const size_t hoff = (size_t)h * DH;
    const float* qp = g_q + ((size_t)(b * S + r)) * H + hoff;
    const float qa = qp[lane];
    const float qb = qp[lane + 32];

    // dot with k_r
    const float* k1 = g_k + ((size_t)(b * S + r)) * H + hoff;
    float d1 = qa * k1[lane] + qb * k1[lane + 32];
    // dot with k_{r-1}
    float d0 = 0.0f;
    if (r > 0) {
        const float* k0 = g_k + ((size_t)(b * S + r - 1)) * H + hoff;
        d0 = qa * k0[lane] + qb * k0[lane + 32];
    }
#pragma unroll
    for (int off = 16; off > 0; off >>= 1) {
        d1 += __shfl_xor_sync(0xFFFFFFFFu, d1, off);
        d0 += __shfl_xor_sync(0xFFFFFFFFu, d0, off);
    }

    const float sc1 = d1 * 0.125f * gate[((size_t)b * S + r) * S + r] + amask[b * S + r];
    float sc0 = NEGV;
    if (r > 0)
        sc0 = d0 * 0.125f * gate[((size_t)b * S + r) * S + (r - 1)] + amask[b * S + r - 1];

    // scores row: NEG everywhere except cols r-1, r
    float* srow = scores_out + ((size_t)((b * NHEADS + h) * S + r)) * S;
#pragma unroll
    for (int i = 0; i < 8; i++) {
        const int c0 = (lane + i * 32) * 4;
        float4 vv = {NEGV, NEGV, NEGV, NEGV};
        if (r - 1 >= c0 && r - 1 < c0 + 4) ((float*)&vv)[r - 1 - c0] = sc0;
        if (r     >= c0 && r     < c0 + 4) ((float*)&vv)[r - c0]     = sc1;
        *(float4*)(srow + c0) = vv;
    }

    // softmax over {sc0, sc1} (masked entries underflow to exactly 0)
    const float m  = fmaxf(sc0, sc1);
    const float e0 = __expf(sc0 - m);
    const float e1 = __expf(sc1 - m);
    const float inv = 1.0f / (e0 + e1);
    const float p0 = e0 * inv, p1 = e1 * inv;

    const float* v1 = g_v + ((size_t)(b * S + r)) * H + hoff;
    const float* v0 = g_v + ((size_t)(b * S + (r > 0 ? r - 1 : 0))) * H + hoff;
    float* orow = out + ((size_t)(b * S + r)) * H + hoff;
    orow[lane]      = p0 * v0[lane]      + p1 * v1[lane];
    orow[lane + 32] = p0 * v0[lane + 32] + p1 * v1[lane + 32];
}

// =================================================================================
// Kernel 2b: row 511 — fully dense. One block per (b,h). grid = 48, block = 256.
// =================================================================================
__global__ void __launch_bounds__(256) row511_kernel(
    const float* __restrict__ gate, const float* __restrict__ amask,
    float* __restrict__ out, float* __restrict__ scores_out)
{
    const int bh = blockIdx.x;
    const int b = bh / NHEADS, h = bh % NHEADS;
    const int r = PROX - 1;                       // 511
    const int tid = threadIdx.x;
    const int lane = tid & 31, w = tid >> 5;

    __shared__ float p[S];
    __shared__ float qsm[DH];
    __shared__ float red[8];
    __shared__ float osum[4][DH];

    if (tid < DH) qsm[tid] = g_q[((size_t)(b * S + r)) * H + h * DH + tid];
    __syncthreads();

    float sc[4];
    float* srow = scores_out + ((size_t)((b * NHEADS + h) * S + r)) * S;
#pragma unroll
    for (int i = 0; i < 4; i++) {
        const int c = tid + i * 256;
        const float* kp = g_k + ((size_t)(b * S + c)) * H + h * DH;
        float d = 0.0f;
#pragma unroll
        for (int e = 0; e < DH; e++) d += qsm[e] * kp[e];
        sc[i] = d * 0.125f * gate[((size_t)b * S + r) * S + c] + amask[b * S + c];
        p[c] = sc[i];
        srow[c] = sc[i];
    }

    // block max
    float m = fmaxf(fmaxf(sc[0], sc[1]), fmaxf(sc[2], sc[3]));
#pragma unroll
    for (int off = 16; off > 0; off >>= 1)
        m = fmaxf(m, __shfl_xor_sync(0xFFFFFFFFu, m, off));
    if (lane == 0) red[w] = m;
    __syncthreads();
    if (tid == 0) {
        float mm = red[0];
#pragma unroll
        for (int i = 1; i < 8; i++) mm = fmaxf(mm, red[i]);
        red[0] = mm;
    }
    __syncthreads();
    m = red[0];
    __syncthreads();

    // exp + sum
    float s = 0.0f;
#pragma unroll
    for (int i = 0; i < 4; i++) {
        const int c = tid + i * 256;
        const float e = __expf(p[c] - m);
        p[c] = e;
        s += e;
    }
#pragma unroll
    for (int off = 16; off > 0; off >>= 1)
        s += __shfl_xor_sync(0xFFFFFFFFu, s, off);
    if (lane == 0) red[w] = s;
    __syncthreads();
    if (tid == 0) {
        float ss = 0.0f;
#pragma unroll
        for (int i = 0; i < 8; i++) ss += red[i];
        red[0] = 1.0f / ss;
    }
    __syncthreads();
    const float inv = red[0];
#pragma unroll
    for (int i = 0; i < 4; i++) p[tid + i * 256] *= inv;
    __syncthreads();

    // PV: part = tid>>6 handles 256 k-rows; d = tid&63
    const int part = tid >> 6, d = tid & 63;
    float acc = 0.0f;
    for (int c = part * 256; c < part * 256 + 256; c++)
        acc += p[c] * g_v[((size_t)(b * S + c)) * H + h * DH + d];
    osum[part][d] = acc;
    __syncthreads();
    if (tid < DH)
        out[((size_t)(b * S + r)) * H + h * DH + tid] =
            osum[0][tid] + osum[1][tid] + osum[2][tid] + osum[3][tid];
}

// =================================================================================
// Kernel 2c: rows 512..1023.  Surviving cols = [Lc, 512), Lc = clamp(feat_len-1,0,512).
// grid = (16, 12, 4): 32 q-rows per block, 256 threads.
// SMEM: Ps[32][516] | Qt[64][36] | KV[8704] = 110080 B dynamic.
// =================================================================================
#define C_PS   0
#define C_QT   (32 * 516)
#define C_KV   (32 * 516 + 64 * 36)
#define C_FLOATS (32 * 516 + 64 * 36 + 8704)
#define C_SMEM_BYTES (C_FLOATS * 4)

__global__ void __launch_bounds__(256) blk_kernel(
    const float* __restrict__ gate, const float* __restrict__ amask,
    const int* __restrict__ feat_len,
    float* __restrict__ out, float* __restrict__ scores_out)
{
    extern __shared__ float sm[];
    float* Ps = sm + C_PS;    // [32][516]
    float* Qt = sm + C_QT;    // [64][36]
    float* KV = sm + C_KV;    // Kt[64][132] (phase A) / Vs[128][68] (phase C)

    const int qt = blockIdx.x;
    const int h  = blockIdx.y;
    const int b  = blockIdx.z;
    const int q0 = PROX + qt * 32;
    const int tid = threadIdx.x;

    const int flm1 = feat_len[b] - 1;
    int Lc = flm1 < 0 ? 0 : flm1;
    if (Lc > PROX) Lc = PROX;
    const int n = PROX - Lc;

    const size_t srow0 = (size_t)((b * NHEADS + h) * S + q0) * S;

    if (n == 0) {
        // entire rows masked -> scores all NEG, probs uniform 1/1024 -> out = mean(V)
        const float4 neg4 = {NEGV, NEGV, NEGV, NEGV};
        for (int idx = tid; idx < 32 * 256; idx += 256) {
            const int rr = idx >> 8;
            const int c4 = (idx & 255) * 4;
            *(float4*)(scores_out + srow0 + (size_t)rr * S + c4) = neg4;
        }
        const int part = tid >> 6, d = tid & 63;
        float acc = 0.0f;
        for (int c = part * 256; c < part * 256 + 256; c++)
            acc += g_v[((size_t)(b * S + c)) * H + h * DH + d];
        sm[part * 64 + d] = acc;
        __syncthreads();
        if (tid < DH) {
            const float mv = (sm[tid] + sm[64 + tid] + sm[128 + tid] + sm[192 + tid])
                             * (1.0f / 1024.0f);
            for (int rr = 0; rr < 32; rr++)
                out[((size_t)(b * S + q0 + rr)) * H + h * DH + tid] = mv;
        }
        return;
    }

    const int kt0 = Lc & ~127;       // first 128-col tile containing Lc

    // ---- NEG fill: cols [512,1024) for all 32 rows ----
    {
        const float4 neg4 = {NEGV, NEGV, NEGV, NEGV};
        for (int idx = tid; idx < 32 * 128; idx += 256) {
            const int rr = idx >> 7;
            const int c4 = (idx & 127) * 4;
            *(float4*)(scores_out + srow0 + (size_t)rr * S + 512 + c4) = neg4;
        }
        // cols [0, kt0)
        const int nA = kt0 >> 2;     // float4 count per row (0..96)
        if (nA > 0) {
            for (int idx = tid; idx < 32 * nA; idx += 256) {
                const int rr = idx / nA;
                const int c4 = (idx % nA) * 4;
                *(float4*)(scores_out + srow0 + (size_t)rr * S + c4) = neg4;
            }
        }
    }

    // ---- load Q tile transposed: Qt[d][r], rows q0..q0+31 ----
#pragma unroll
    for (int it = 0; it < 2; it++) {
        const int idx = tid + it * 256;
        const int r   = idx >> 4;
        const int d4  = (idx & 15) * 4;
        const float4 v = *(const float4*)&g_q[(size_t)(b * S + q0 + r) * H + h * DH + d4];
        Qt[(d4 + 0) * 36 + r] = v.x;
        Qt[(d4 + 1) * 36 + r] = v.y;
        Qt[(d4 + 2) * 36 + r] = v.z;
        Qt[(d4 + 3) * 36 + r] = v.w;
    }

    const int qg = tid >> 5;         // 0..7
    const int kg = tid & 31;         // 0..31
    const int qr = qg * 4;

    // ================= Phase A: scores over col tiles [kt0, 512) =================
    for (int kt = kt0; kt < PROX; kt += 128) {
        __syncthreads();
        // load Kt[64][132], k-rows kt..kt+127 transposed
#pragma unroll
        for (int it = 0; it < 8; it++) {
            const int idx = tid + it * 256;      // 0..2047 (float4 units)
            const int r   = idx >> 4;            // 0..127
            const int d4  = (idx & 15) * 4;
            const float4 v = *(const float4*)&g_k[(size_t)(b * S + kt + r) * H + h * DH + d4];
            KV[(d4 + 0) * 132 + r] = v.x;
            KV[(d4 + 1) * 132 + r] = v.y;
            KV[(d4 + 2) * 132 + r] = v.z;
            KV[(d4 + 3) * 132 + r] = v.w;
        }
        __syncthreads();

        float acc[4][4];
#pragma unroll
        for (int i = 0; i < 4; i++)
#pragma unroll
            for (int j = 0; j < 4; j++) acc[i][j] = 0.0f;

#pragma unroll 16
        for (int d = 0; d < 64; d++) {
            const float4 a4 = *(const float4*)&Qt[d * 36 + qr];
            const float4 b4 = *(const float4*)&KV[d * 132 + kg * 4];
            const float a[4] = {a4.x, a4.y, a4.z, a4.w};
            const float bb[4] = {b4.x, b4.y, b4.z, b4.w};
#pragma unroll
            for (int i = 0; i < 4; i++)
#pragma unroll
                for (int j = 0; j < 4; j++) acc[i][j] += a[i] * bb[j];
        }

        const int kbase = kt + kg * 4;
        const float4 am = *(const float4*)&amask[b * S + kbase];
        const float amv[4] = {am.x, am.y, am.z, am.w};
#pragma unroll
        for (int i = 0; i < 4; i++) {
            const int qrow = q0 + qr + i;
            const float4 g = *(const float4*)&gate[((size_t)b * S + qrow) * S + kbase];
            const float gg[4] = {g.x, g.y, g.z, g.w};
            float sc[4];
#pragma unroll
            for (int j = 0; j < 4; j++) {
                const int kc = kbase + j;
                const float v = acc[i][j] * 0.125f * gg[j] + amv[j];
                sc[j] = (kc < Lc) ? NEGV : v;
            }
            const float4 s4 = {sc[0], sc[1], sc[2], sc[3]};
            *(float4*)&Ps[(qr + i) * 516 + kbase] = s4;
            *(float4*)(scores_out + srow0 + (size_t)(qr + i) * S + kbase) = s4;
        }
    }
    __syncthreads();

    // ================= Phase B: softmax over cols [kt0, 512) =================
    {
        const int lane = tid & 31;
        const int w    = tid >> 5;
#pragma unroll
        for (int rr = 0; rr < 4; rr++) {
            float* row = Ps + (w * 4 + rr) * 516;
            float m = -3.4e38f;
            for (int c = kt0 + lane; c < PROX; c += 32) m = fmaxf(m, row[c]);
#pragma unroll
            for (int off = 16; off > 0; off >>= 1)
                m = fmaxf(m, __shfl_xor_sync(0xFFFFFFFFu, m, off));
            float ssum = 0.0f;
            for (int c = kt0 + lane; c < PROX; c += 32) {
                const float e = __expf(row[c] - m);
                row[c] = e;
                ssum += e;
            }
#pragma unroll
            for (int off = 16; off > 0; off >>= 1)
                ssum += __shfl_xor_sync(0xFFFFFFFFu, ssum, off);
            const float inv = 1.0f / ssum;
            for (int c = kt0 + lane; c < PROX; c += 32) row[c] *= inv;
        }
    }
    __syncthreads();

    // ================= Phase C: out = P @ V over k in [kt0, 512) =================
    float oacc[4][2];
#pragma unroll
    for (int i = 0; i < 4; i++) { oacc[i][0] = 0.0f; oacc[i][1] = 0.0f; }

    for (int kt = kt0; kt < PROX; kt += 128) {
        // load Vs[128][68]
#pragma unroll
        for (int it = 0; it < 8; it++) {
            const int idx = tid + it * 256;
            const int r   = idx >> 4;
            const int d4  = (idx & 15) * 4;
            *(float4*)&KV[r * 68 + d4] =
                *(const float4*)&g_v[(size_t)(b * S + kt + r) * H + h * DH + d4];
        }
        __syncthreads();

#pragma unroll 2
        for (int k = 0; k < 128; k += 4) {
            float4 pv[4];
#pragma unroll
            for (int i = 0; i < 4; i++)
                pv[i] = *(const float4*)&Ps[(qr + i) * 516 + kt + k];
#pragma unroll
            for (int j = 0; j < 4; j++) {
                const float v0 = KV[(k + j) * 68 + kg];
                const float v1 = KV[(k + j) * 68 + kg + 32];
                const float pj[4] = {
                    j == 0 ? pv[0].x : j == 1 ? pv[0].y : j == 2 ? pv[0].z : pv[0].w,
                    j == 0 ? pv[1].x : j == 1 ? pv[1].y : j == 2 ? pv[1].z : pv[1].w,
                    j == 0 ? pv[2].x : j == 1 ? pv[2].y : j == 2 ? pv[2].z : pv[2].w,
                    j == 0 ? pv[3].x : j == 1 ? pv[3].y : j == 2 ? pv[3].z : pv[3].w };
#pragma unroll
                for (int i = 0; i < 4; i++) {
                    oacc[i][0] += pj[i] * v0;
                    oacc[i][1] += pj[i] * v1;
                }
            }
        }
        __syncthreads();
    }

#pragma unroll
    for (int i = 0; i < 4; i++) {
        const size_t ooff = (size_t)(b * S + q0 + qr + i) * H + h * DH;
        out[ooff + kg]      = oacc[i][0];
        out[ooff + kg + 32] = oacc[i][1];
    }
}

// =================================================================================
extern "C" void kernel_launch(void* const* d_in, const int* in_sizes, int n_in,
                              void* d_out, int out_size) {
    const float* hidden   = (const float*)d_in[0];
    const float* context  = (const float*)d_in[1];
    const float* amask    = (const float*)d_in[2];   // (B,1,1,S)
    const float* gate     = (const float*)d_in[3];   // (B,1,S,S)
    const float* vis      = (const float*)d_in[4];
    const float* Wq       = (const float*)d_in[5];
    const float* bq       = (const float*)d_in[6];
    const float* Wk       = (const float*)d_in[7];
    const float* bk       = (const float*)d_in[8];
    const float* Wv       = (const float*)d_in[9];
    const float* bv       = (const float*)d_in[10];
    const int*   feat_len = (const int*)d_in[11];
    // d_in[12] = prox_pos (constant 512, hardcoded)

    float* out_ptr = (float*)d_out;
    float* scores_ptr = out_ptr + (size_t)BATCH * S * H;

    qkv_gemm<<<dim3(6, 32, 3), 256>>>(hidden, context, vis, feat_len,
                                      Wq, bq, Wk, bk, Wv, bv);

    band_kernel<<<dim3(64, NHEADS, BATCH), 256>>>(gate, amask, out_ptr, scores_ptr);
    row511_kernel<<<dim3(BATCH * NHEADS), 256>>>(gate, amask, out_ptr, scores_ptr);

    cudaFuncSetAttribute(blk_kernel, cudaFuncAttributeMaxDynamicSharedMemorySize,
                         C_SMEM_BYTES);
    blk_kernel<<<dim3(16, NHEADS, BATCH), 256, C_SMEM_BYTES>>>(
        gate, amask, feat_len, out_ptr, scores_ptr);
}

// round 3
// speedup vs baseline: 3.1232x; 1.5006x over previous
#include <cuda_runtime.h>
#include <cuda_bf16.h>
#include <cstdint>
#include <cstddef>

#define S 1024
#define H 768
#define NHEADS 12
#define DH 64
#define BATCH 4
#define PROX 512
#define NEGV (-100000.0f)

// ---------------- scratch (allocation-free rule: device globals) ----------------
__device__ float g_q[(size_t)BATCH * S * H];
__device__ float g_k[(size_t)BATCH * S * H];
__device__ float g_v[(size_t)BATCH * S * H];

// =================================================================================
// Kernel 1: fused (x + masked vis) @ W^T + b for Q/K/V, bf16 split-MMA (3xBF16).
// C = A @ W^T: A[4096x768], W[768x768].  Block 128x64, 8 warps (4M x 2N),
// warp tile 32x32 = 2 x m16 * 4 x n8, mma.m16n8k16.bf16, fp32 accum.
// a = a_hi + a_lo (bf16 each); C ≈ ah*bh + ah*bl + al*bh  (error ~2^-18)
// grid = (12, 32, 3)
// =================================================================================
#define PITCH 20   // uint32 words per row (16 k-pairs + pad) -> conflict-free quads

__device__ __forceinline__ void bsplit2(float x, float y, uint32_t& hi, uint32_t& lo) {
    __nv_bfloat16 hx = __float2bfloat16(x);
    __nv_bfloat16 hy = __float2bfloat16(y);
    float rx = x - __bfloat162float(hx);
    float ry = y - __bfloat162float(hy);
    __nv_bfloat162 h2; h2.x = hx; h2.y = hy;
    __nv_bfloat162 l2; l2.x = __float2bfloat16(rx); l2.y = __float2bfloat16(ry);
    hi = *(uint32_t*)&h2;
    lo = *(uint32_t*)&l2;
}

__device__ __forceinline__ void mma_bf16(float* c, const uint32_t* a, const uint32_t* b) {
    asm volatile(
        "mma.sync.aligned.m16n8k16.row.col.f32.bf16.bf16.f32 "
        "{%0,%1,%2,%3}, {%4,%5,%6,%7}, {%8,%9}, {%0,%1,%2,%3};"
        : "+f"(c[0]), "+f"(c[1]), "+f"(c[2]), "+f"(c[3])
        : "r"(a[0]), "r"(a[1]), "r"(a[2]), "r"(a[3]), "r"(b[0]), "r"(b[1]));
}

__global__ void __launch_bounds__(256, 2) qkv_gemm(
    const float* __restrict__ hidden, const float* __restrict__ context,
    const float* __restrict__ vis, const int* __restrict__ feat_len,
    const float* __restrict__ Wq, const float* __restrict__ bq,
    const float* __restrict__ Wk, const float* __restrict__ bk,
    const float* __restrict__ Wv, const float* __restrict__ bv)
{
    const int z = blockIdx.z;
    const float* A = (z == 0) ? hidden : context;
    const float* W;
    const float* bias;
    float* C;
    if (z == 0)      { W = Wq; bias = bq; C = g_q; }
    else if (z == 1) { W = Wk; bias = bk; C = g_k; }
    else             { W = Wv; bias = bv; C = g_v; }

    const int m0 = blockIdx.y * 128;
    const int n0 = blockIdx.x * 64;
    const int b  = m0 >> 10;                 // 128-row tile never crosses a batch
    const int fl = feat_len[b];

    __shared__ uint32_t Ahi[128 * PITCH];
    __shared__ uint32_t Alo[128 * PITCH];
    __shared__ uint32_t Bhi[64 * PITCH];
    __shared__ uint32_t Blo[64 * PITCH];

    const int tid  = threadIdx.x;
    const int lane = tid & 31;
    const int warp = tid >> 5;
    const int wm = warp & 3;                 // 0..3  (M)
    const int wn = warp >> 2;                // 0..1  (N)
    const int l4 = lane & 3;                 // threadID in group
    const int g8 = lane >> 2;                // group

    float c[2][4][4];
#pragma unroll
    for (int mi = 0; mi < 2; mi++)
#pragma unroll
        for (int ni = 0; ni < 4; ni++)
#pragma unroll
            for (int e = 0; e < 4; e++) c[mi][ni][e] = 0.0f;

    for (int k0 = 0; k0 < H; k0 += 32) {
        __syncthreads();
        // ---- load + split A tile [128][32] ----
#pragma unroll
        for (int it = 0; it < 4; it++) {
            const int fid = tid + it * 256;       // 0..1023
            const int row = fid >> 3;             // 0..127
            const int kq  = (fid & 7) * 4;        // 0..28
            float4 av = *(const float4*)&A[(size_t)(m0 + row) * H + k0 + kq];
            if (((m0 + row) & (S - 1)) < fl) {
                const float4 vv = *(const float4*)&vis[(size_t)(m0 + row) * H + k0 + kq];
                av.x += vv.x; av.y += vv.y; av.z += vv.z; av.w += vv.w;
            }
            uint32_t h0, l0, h1, l1;
            bsplit2(av.x, av.y, h0, l0);
            bsplit2(av.z, av.w, h1, l1);
            const int base = row * PITCH + (kq >> 1);
            Ahi[base] = h0; Ahi[base + 1] = h1;
            Alo[base] = l0; Alo[base + 1] = l1;
        }
        // ---- load + split B tile [64][32] (B[n][k] = W[n0+n][k0+k]) ----
#pragma unroll
        for (int it = 0; it < 2; it++) {
            const int fid = tid + it * 256;       // 0..511
            const int row = fid >> 3;             // 0..63
            const int kq  = (fid & 7) * 4;
            const float4 wv = *(const float4*)&W[(size_t)(n0 + row) * H + k0 + kq];
            uint32_t h0, l0, h1, l1;
            bsplit2(wv.x, wv.y, h0, l0);
            bsplit2(wv.z, wv.w, h1, l1);
            const int base = row * PITCH + (kq >> 1);
            Bhi[base] = h0; Bhi[base + 1] = h1;
            Blo[base] = l0; Blo[base + 1] = l1;
        }
        __syncthreads();

#pragma unroll
        for (int kk = 0; kk < 2; kk++) {
            const int pb = kk * 8;                // pair base for this k16 step
            uint32_t bh[4][2], bl[4][2];
#pragma unroll
            for (int ni = 0; ni < 4; ni++) {
                const int n = (wn * 32 + ni * 8 + g8) * PITCH + pb + l4;
                bh[ni][0] = Bhi[n];     bh[ni][1] = Bhi[n + 4];
                bl[ni][0] = Blo[n];     bl[ni][1] = Blo[n + 4];
            }
#pragma unroll
            for (int mi = 0; mi < 2; mi++) {
                const int r0 = (wm * 32 + mi * 16 + g8) * PITCH + pb + l4;
                const int r1 = r0 + 8 * PITCH;
                uint32_t ah[4], al[4];
                ah[0] = Ahi[r0];     ah[1] = Ahi[r1];
                ah[2] = Ahi[r0 + 4]; ah[3] = Ahi[r1 + 4];
                al[0] = Alo[r0];     al[1] = Alo[r1];
                al[2] = Alo[r0 + 4]; al[3] = Alo[r1 + 4];
#pragma unroll
                for (int ni = 0; ni < 4; ni++) {
                    mma_bf16(c[mi][ni], ah, bh[ni]);
                    mma_bf16(c[mi][ni], ah, bl[ni]);
                    mma_bf16(c[mi][ni], al, bh[ni]);
                }
            }
        }
    }

    // ---- epilogue: + bias, store float2 pairs ----
#pragma unroll
    for (int mi = 0; mi < 2; mi++) {
#pragma unroll
        for (int ni = 0; ni < 4; ni++) {
            const int col = n0 + wn * 32 + ni * 8 + l4 * 2;
            const float2 bi = *(const float2*)&bias[col];
            const int row0 = m0 + wm * 32 + mi * 16 + g8;
            float2 v0 = {c[mi][ni][0] + bi.x, c[mi][ni][1] + bi.y};
            float2 v1 = {c[mi][ni][2] + bi.x, c[mi][ni][3] + bi.y};
            *(float2*)&C[(size_t)row0 * H + col]       = v0;
            *(float2*)&C[(size_t)(row0 + 8) * H + col] = v1;
        }
    }
}

// =================================================================================
// Kernel 2a: band rows r in [0, 511).  Only cols {r-1, r} survive the mask.
// =================================================================================
__global__ void __launch_bounds__(256) band_kernel(
    const float* __restrict__ gate, const float* __restrict__ amask,
    float* __restrict__ out, float* __restrict__ scores_out)
{
    const int lane = threadIdx.x & 31;
    const int w    = threadIdx.x >> 5;
    const int r    = blockIdx.x * 8 + w;
    if (r >= PROX - 1) return;
    const int h = blockIdx.y;
    const int b = blockIdx.z;

    const size_t hoff = (size_t)h * DH;
    const float* qp = g_q + ((size_t)(b * S + r)) * H + hoff;
    const float qa = qp[lane];
    const float qb = qp[lane + 32];

    const float* k1 = g_k + ((size_t)(b * S + r)) * H + hoff;
    float d1 = qa * k1[lane] + qb * k1[lane + 32];
    float d0 = 0.0f;
    if (r > 0) {
        const float* k0 = g_k + ((size_t)(b * S + r - 1)) * H + hoff;
        d0 = qa * k0[lane] + qb * k0[lane + 32];
    }
#pragma unroll
    for (int off = 16; off > 0; off >>= 1) {
        d1 += __shfl_xor_sync(0xFFFFFFFFu, d1, off);
        d0 += __shfl_xor_sync(0xFFFFFFFFu, d0, off);
    }

    const float sc1 = d1 * 0.125f * gate[((size_t)b * S + r) * S + r] + amask[b * S + r];
    float sc0 = NEGV;
    if (r > 0)
        sc0 = d0 * 0.125f * gate[((size_t)b * S + r) * S + (r - 1)] + amask[b * S + r - 1];

    float* srow = scores_out + ((size_t)((b * NHEADS + h) * S + r)) * S;
#pragma unroll
    for (int i = 0; i < 8; i++) {
        const int c0 = (lane + i * 32) * 4;
        float4 vv = {NEGV, NEGV, NEGV, NEGV};
        if (r - 1 >= c0 && r - 1 < c0 + 4) ((float*)&vv)[r - 1 - c0] = sc0;
        if (r     >= c0 && r     < c0 + 4) ((float*)&vv)[r - c0]     = sc1;
        *(float4*)(srow + c0) = vv;
    }

    const float m  = fmaxf(sc0, sc1);
    const float e0 = __expf(sc0 - m);
    const float e1 = __expf(sc1 - m);
    const float inv = 1.0f / (e0 + e1);
    const float p0 = e0 * inv, p1 = e1 * inv;

    const float* v1 = g_v + ((size_t)(b * S + r)) * H + hoff;
    const float* v0 = g_v + ((size_t)(b * S + (r > 0 ? r - 1 : 0))) * H + hoff;
    float* orow = out + ((size_t)(b * S + r)) * H + hoff;
    orow[lane]      = p0 * v0[lane]      + p1 * v1[lane];
    orow[lane + 32] = p0 * v0[lane + 32] + p1 * v1[lane + 32];
}

// =================================================================================
// Kernel 2b: row 511 — fully dense. One block per (b,h). grid = 48, block = 256.
// =================================================================================
__global__ void __launch_bounds__(256) row511_kernel(
    const float* __restrict__ gate, const float* __restrict__ amask,
    float* __restrict__ out, float* __restrict__ scores_out)
{
    const int bh = blockIdx.x;
    const int b = bh / NHEADS, h = bh % NHEADS;
    const int r = PROX - 1;
    const int tid = threadIdx.x;
    const int lane = tid & 31, w = tid >> 5;

    __shared__ float p[S];
    __shared__ float qsm[DH];
    __shared__ float red[8];
    __shared__ float osum[4][DH];

    if (tid < DH) qsm[tid] = g_q[((size_t)(b * S + r)) * H + h * DH + tid];
    __syncthreads();

    float sc[4];
    float* srow = scores_out + ((size_t)((b * NHEADS + h) * S + r)) * S;
#pragma unroll
    for (int i = 0; i < 4; i++) {
        const int c = tid + i * 256;
        const float* kp = g_k + ((size_t)(b * S + c)) * H + h * DH;
        float d = 0.0f;
#pragma unroll
        for (int e = 0; e < DH; e++) d += qsm[e] * kp[e];
        sc[i] = d * 0.125f * gate[((size_t)b * S + r) * S + c] + amask[b * S + c];
        p[c] = sc[i];
        srow[c] = sc[i];
    }

    float m = fmaxf(fmaxf(sc[0], sc[1]), fmaxf(sc[2], sc[3]));
#pragma unroll
    for (int off = 16; off > 0; off >>= 1)
        m = fmaxf(m, __shfl_xor_sync(0xFFFFFFFFu, m, off));
    if (lane == 0) red[w] = m;
    __syncthreads();
    if (tid == 0) {
        float mm = red[0];
#pragma unroll
        for (int i = 1; i < 8; i++) mm = fmaxf(mm, red[i]);
        red[0] = mm;
    }
    __syncthreads();
    m = red[0];
    __syncthreads();

    float s = 0.0f;
#pragma unroll
    for (int i = 0; i < 4; i++) {
        const int c = tid + i * 256;
        const float e = __expf(p[c] - m);
        p[c] = e;
        s += e;
    }
#pragma unroll
    for (int off = 16; off > 0; off >>= 1)
        s += __shfl_xor_sync(0xFFFFFFFFu, s, off);
    if (lane == 0) red[w] = s;
    __syncthreads();
    if (tid == 0) {
        float ss = 0.0f;
#pragma unroll
        for (int i = 0; i < 8; i++) ss += red[i];
        red[0] = 1.0f / ss;
    }
    __syncthreads();
    const float inv = red[0];
#pragma unroll
    for (int i = 0; i < 4; i++) p[tid + i * 256] *= inv;
    __syncthreads();

    const int part = tid >> 6, d = tid & 63;
    float acc = 0.0f;
    for (int c = part * 256; c < part * 256 + 256; c++)
        acc += p[c] * g_v[((size_t)(b * S + c)) * H + h * DH + d];
    osum[part][d] = acc;
    __syncthreads();
    if (tid < DH)
        out[((size_t)(b * S + r)) * H + h * DH + tid] =
            osum[0][tid] + osum[1][tid] + osum[2][tid] + osum[3][tid];
}

// =================================================================================
// Kernel 2c: rows 512..1023.  Surviving cols = [Lc, 512).
// =================================================================================
#define C_PS   0
#define C_QT   (32 * 516)
#define C_KV   (32 * 516 + 64 * 36)
#define C_FLOATS (32 * 516 + 64 * 36 + 8704)
#define C_SMEM_BYTES (C_FLOATS * 4)

__global__ void __launch_bounds__(256) blk_kernel(
    const float* __restrict__ gate, const float* __restrict__ amask,
    const int* __restrict__ feat_len,
    float* __restrict__ out, float* __restrict__ scores_out)
{
    extern __shared__ float sm[];
    float* Ps = sm + C_PS;
    float* Qt = sm + C_QT;
    float* KV = sm + C_KV;

    const int qt = blockIdx.x;
    const int h  = blockIdx.y;
    const int b  = blockIdx.z;
    const int q0 = PROX + qt * 32;
    const int tid = threadIdx.x;

    const int flm1 = feat_len[b] - 1;
    int Lc = flm1 < 0 ? 0 : flm1;
    if (Lc > PROX) Lc = PROX;
    const int n = PROX - Lc;

    const size_t srow0 = (size_t)((b * NHEADS + h) * S + q0) * S;

    if (n == 0) {
        const float4 neg4 = {NEGV, NEGV, NEGV, NEGV};
        for (int idx = tid; idx < 32 * 256; idx += 256) {
            const int rr = idx >> 8;
            const int c4 = (idx & 255) * 4;
            *(float4*)(scores_out + srow0 + (size_t)rr * S + c4) = neg4;
        }
        const int part = tid >> 6, d = tid & 63;
        float acc = 0.0f;
        for (int c = part * 256; c < part * 256 + 256; c++)
            acc += g_v[((size_t)(b * S + c)) * H + h * DH + d];
        sm[part * 64 + d] = acc;
        __syncthreads();
        if (tid < DH) {
            const float mv = (sm[tid] + sm[64 + tid] + sm[128 + tid] + sm[192 + tid])
                             * (1.0f / 1024.0f);
            for (int rr = 0; rr < 32; rr++)
                out[((size_t)(b * S + q0 + rr)) * H + h * DH + tid] = mv;
        }
        return;
    }

    const int kt0 = Lc & ~127;

    {
        const float4 neg4 = {NEGV, NEGV, NEGV, NEGV};
        for (int idx = tid; idx < 32 * 128; idx += 256) {
            const int rr = idx >> 7;
            const int c4 = (idx & 127) * 4;
            *(float4*)(scores_out + srow0 + (size_t)rr * S + 512 + c4) = neg4;
        }
        const int nA = kt0 >> 2;
        if (nA > 0) {
            for (int idx = tid; idx < 32 * nA; idx += 256) {
                const int rr = idx / nA;
                const int c4 = (idx % nA) * 4;
                *(float4*)(scores_out + srow0 + (size_t)rr * S + c4) = neg4;
            }
        }
    }

#pragma unroll
    for (int it = 0; it < 2; it++) {
        const int idx = tid + it * 256;
        const int r   = idx >> 4;
        const int d4  = (idx & 15) * 4;
        const float4 v = *(const float4*)&g_q[(size_t)(b * S + q0 + r) * H + h * DH + d4];
        Qt[(d4 + 0) * 36 + r] = v.x;
        Qt[(d4 + 1) * 36 + r] = v.y;
        Qt[(d4 + 2) * 36 + r] = v.z;
        Qt[(d4 + 3) * 36 + r] = v.w;
    }

    const int qg = tid >> 5;
    const int kg = tid & 31;
    const int qr = qg * 4;

    for (int kt = kt0; kt < PROX; kt += 128) {
        __syncthreads();
#pragma unroll
        for (int it = 0; it < 8; it++) {
            const int idx = tid + it * 256;
            const int r   = idx >> 4;
            const int d4  = (idx & 15) * 4;
            const float4 v = *(const float4*)&g_k[(size_t)(b * S + kt + r) * H + h * DH + d4];
            KV[(d4 + 0) * 132 + r] = v.x;
            KV[(d4 + 1) * 132 + r] = v.y;
            KV[(d4 + 2) * 132 + r] = v.z;
            KV[(d4 + 3) * 132 + r] = v.w;
        }
        __syncthreads();

        float acc[4][4];
#pragma unroll
        for (int i = 0; i < 4; i++)
#pragma unroll
            for (int j = 0; j < 4; j++) acc[i][j] = 0.0f;

#pragma unroll 16
        for (int d = 0; d < 64; d++) {
            const float4 a4 = *(const float4*)&Qt[d * 36 + qr];
            const float4 b4 = *(const float4*)&KV[d * 132 + kg * 4];
            const float a[4] = {a4.x, a4.y, a4.z, a4.w};
            const float bb[4] = {b4.x, b4.y, b4.z, b4.w};
#pragma unroll
            for (int i = 0; i < 4; i++)
#pragma unroll
                for (int j = 0; j < 4; j++) acc[i][j] += a[i] * bb[j];
        }

        const int kbase = kt + kg * 4;
        const float4 am = *(const float4*)&amask[b * S + kbase];
        const float amv[4] = {am.x, am.y, am.z, am.w};
#pragma unroll
        for (int i = 0; i < 4; i++) {
            const int qrow = q0 + qr + i;
            const float4 g = *(const float4*)&gate[((size_t)b * S + qrow) * S + kbase];
            const float gg[4] = {g.x, g.y, g.z, g.w};
            float sc[4];
#pragma unroll
            for (int j = 0; j < 4; j++) {
                const int kc = kbase + j;
                const float v = acc[i][j] * 0.125f * gg[j] + amv[j];
                sc[j] = (kc < Lc) ? NEGV : v;
            }
            const float4 s4 = {sc[0], sc[1], sc[2], sc[3]};
            *(float4*)&Ps[(qr + i) * 516 + kbase] = s4;
            *(float4*)(scores_out + srow0 + (size_t)(qr + i) * S + kbase) = s4;
        }
    }
    __syncthreads();

    {
        const int lane = tid & 31;
        const int w    = tid >> 5;
#pragma unroll
        for (int rr = 0; rr < 4; rr++) {
            float* row = Ps + (w * 4 + rr) * 516;
            float m = -3.4e38f;
            for (int c = kt0 + lane; c < PROX; c += 32) m = fmaxf(m, row[c]);
#pragma unroll
            for (int off = 16; off > 0; off >>= 1)
                m = fmaxf(m, __shfl_xor_sync(0xFFFFFFFFu, m, off));
            float ssum = 0.0f;
            for (int c = kt0 + lane; c < PROX; c += 32) {
                const float e = __expf(row[c] - m);
                row[c] = e;
                ssum += e;
            }
#pragma unroll
            for (int off = 16; off > 0; off >>= 1)
                ssum += __shfl_xor_sync(0xFFFFFFFFu, ssum, off);
            const float inv = 1.0f / ssum;
            for (int c = kt0 + lane; c < PROX; c += 32) row[c] *= inv;
        }
    }
    __syncthreads();

    float oacc[4][2];
#pragma unroll
    for (int i = 0; i < 4; i++) { oacc[i][0] = 0.0f; oacc[i][1] = 0.0f; }

    for (int kt = kt0; kt < PROX; kt += 128) {
#pragma unroll
        for (int it = 0; it < 8; it++) {
            const int idx = tid + it * 256;
            const int r   = idx >> 4;
            const int d4  = (idx & 15) * 4;
            *(float4*)&KV[r * 68 + d4] =
                *(const float4*)&g_v[(size_t)(b * S + kt + r) * H + h * DH + d4];
        }
        __syncthreads();

#pragma unroll 2
        for (int k = 0; k < 128; k += 4) {
            float4 pv[4];
#pragma unroll
            for (int i = 0; i < 4; i++)
                pv[i] = *(const float4*)&Ps[(qr + i) * 516 + kt + k];
#pragma unroll
            for (int j = 0; j < 4; j++) {
                const float v0 = KV[(k + j) * 68 + kg];
                const float v1 = KV[(k + j) * 68 + kg + 32];
                const float pj[4] = {
                    j == 0 ? pv[0].x : j == 1 ? pv[0].y : j == 2 ? pv[0].z : pv[0].w,
                    j == 0 ? pv[1].x : j == 1 ? pv[1].y : j == 2 ? pv[1].z : pv[1].w,
                    j == 0 ? pv[2].x : j == 1 ? pv[2].y : j == 2 ? pv[2].z : pv[2].w,
                    j == 0 ? pv[3].x : j == 1 ? pv[3].y : j == 2 ? pv[3].z : pv[3].w };
#pragma unroll
                for (int i = 0; i < 4; i++) {
                    oacc[i][0] += pj[i] * v0;
                    oacc[i][1] += pj[i] * v1;
                }
            }
        }
        __syncthreads();
    }

#pragma unroll
    for (int i = 0; i < 4; i++) {
        const size_t ooff = (size_t)(b * S + q0 + qr + i) * H + h * DH;
        out[ooff + kg]      = oacc[i][0];
        out[ooff + kg + 32] = oacc[i][1];
    }
}

// =================================================================================
extern "C" void kernel_launch(void* const* d_in, const int* in_sizes, int n_in,
                              void* d_out, int out_size) {
    const float* hidden   = (const float*)d_in[0];
    const float* context  = (const float*)d_in[1];
    const float* amask    = (const float*)d_in[2];
    const float* gate     = (const float*)d_in[3];
    const float* vis      = (const float*)d_in[4];
    const float* Wq       = (const float*)d_in[5];
    const float* bq       = (const float*)d_in[6];
    const float* Wk       = (const float*)d_in[7];
    const float* bk       = (const float*)d_in[8];
    const float* Wv       = (const float*)d_in[9];
    const float* bv       = (const float*)d_in[10];
    const int*   feat_len = (const int*)d_in[11];

    float* out_ptr = (float*)d_out;
    float* scores_ptr = out_ptr + (size_t)BATCH * S * H;

    qkv_gemm<<<dim3(12, 32, 3), 256>>>(hidden, context, vis, feat_len,
                                       Wq, bq, Wk, bk, Wv, bv);

    band_kernel<<<dim3(64, NHEADS, BATCH), 256>>>(gate, amask, out_ptr, scores_ptr);
    row511_kernel<<<dim3(BATCH * NHEADS), 256>>>(gate, amask, out_ptr, scores_ptr);

    cudaFuncSetAttribute(blk_kernel, cudaFuncAttributeMaxDynamicSharedMemorySize,
                         C_SMEM_BYTES);
    blk_kernel<<<dim3(16, NHEADS, BATCH), 256, C_SMEM_BYTES>>>(
        gate, amask, feat_len, out_ptr, scores_ptr);
}

// round 5
// speedup vs baseline: 3.4337x; 1.0994x over previous
#include <cuda_runtime.h>
#include <cuda_bf16.h>
#include <cstdint>
#include <cstddef>

#define S 1024
#define H 768
#define NHEADS 12
#define DH 64
#define BATCH 4
#define PROX 512
#define NEGV (-100000.0f)
#define MROWS (BATCH * S)          // 4096

// ---------------- scratch (allocation-free rule: device globals) ----------------
__device__ float g_q[(size_t)BATCH * S * H];
__device__ float g_k[(size_t)BATCH * S * H];
__device__ float g_v[(size_t)BATCH * S * H];
// pre-split bf16 inputs: [0]=hidden+vis, [1]=context+vis
__device__ __nv_bfloat16 g_ahi[(size_t)2 * MROWS * H];
__device__ __nv_bfloat16 g_alo[(size_t)2 * MROWS * H];
// pre-split weights: [0]=Wq, [1]=Wk, [2]=Wv
__device__ __nv_bfloat16 g_whi[(size_t)3 * H * H];
__device__ __nv_bfloat16 g_wlo[(size_t)3 * H * H];

__device__ __forceinline__ void bsplit2(float x, float y, uint32_t& hi, uint32_t& lo) {
    __nv_bfloat16 hx = __float2bfloat16(x);
    __nv_bfloat16 hy = __float2bfloat16(y);
    float rx = x - __bfloat162float(hx);
    float ry = y - __bfloat162float(hy);
    __nv_bfloat162 h2; h2.x = hx; h2.y = hy;
    __nv_bfloat162 l2; l2.x = __float2bfloat16(rx); l2.y = __float2bfloat16(ry);
    hi = *(uint32_t*)&h2;
    lo = *(uint32_t*)&l2;
}

// =================================================================================
// Pre-pass A: split (x + masked vis) into bf16 hi/lo.  grid = (3072, 2), 256 thr.
// =================================================================================
__global__ void __launch_bounds__(256) split_inputs(
    const float* __restrict__ hidden, const float* __restrict__ context,
    const float* __restrict__ vis, const int* __restrict__ feat_len)
{
    const int z = blockIdx.y;
    const size_t idx = (size_t)blockIdx.x * 256 + threadIdx.x;   // float4 id, 786432 total
    const int row = (int)(idx / 192);                            // 768/4 = 192 float4 per row
    const int fl = feat_len[row >> 10];
    const float* src = z ? context : hidden;
    float4 a = ((const float4*)src)[idx];
    if ((row & (S - 1)) < fl) {
        const float4 vv = ((const float4*)vis)[idx];
        a.x += vv.x; a.y += vv.y; a.z += vv.z; a.w += vv.w;
    }
    uint32_t h0, l0, h1, l1;
    bsplit2(a.x, a.y, h0, l0);
    bsplit2(a.z, a.w, h1, l1);
    ((uint2*)(g_ahi + (size_t)z * MROWS * H))[idx] = make_uint2(h0, h1);
    ((uint2*)(g_alo + (size_t)z * MROWS * H))[idx] = make_uint2(l0, l1);
}

// Pre-pass B: split weights.  grid = (576, 3), 256 thr.
__global__ void __launch_bounds__(256) split_w(
    const float* __restrict__ Wq, const float* __restrict__ Wk,
    const float* __restrict__ Wv)
{
    const int z = blockIdx.y;
    const float* W = (z == 0) ? Wq : (z == 1) ? Wk : Wv;
    const size_t idx = (size_t)blockIdx.x * 256 + threadIdx.x;   // float4 id, 147456 total
    const float4 a = ((const float4*)W)[idx];
    uint32_t h0, l0, h1, l1;
    bsplit2(a.x, a.y, h0, l0);
    bsplit2(a.z, a.w, h1, l1);
    ((uint2*)(g_whi + (size_t)z * H * H))[idx] = make_uint2(h0, h1);
    ((uint2*)(g_wlo + (size_t)z * H * H))[idx] = make_uint2(l0, l1);
}

// =================================================================================
// Kernel 1: C = A @ W^T + b via 3-term bf16 split MMA, pre-split inputs.
// Block 128x64, 8 warps (4M x 2N), warp tile 32x32, k-chunk 64.  grid = (12, 32, 3)
// SMEM (dynamic): Ahi[128*36] Alo[128*36] Bhi[64*36] Blo[64*36] uint32 = 55296 B
// =================================================================================
#define PITCH 36

__device__ __forceinline__ void mma_bf16(float* c, const uint32_t* a, const uint32_t* b) {
    asm volatile(
        "mma.sync.aligned.m16n8k16.row.col.f32.bf16.bf16.f32 "
        "{%0,%1,%2,%3}, {%4,%5,%6,%7}, {%8,%9}, {%0,%1,%2,%3};"
        : "+f"(c[0]), "+f"(c[1]), "+f"(c[2]), "+f"(c[3])
        : "r"(a[0]), "r"(a[1]), "r"(a[2]), "r"(a[3]), "r"(b[0]), "r"(b[1]));
}

#define G_SMEM_BYTES ((128 * PITCH + 128 * PITCH + 64 * PITCH + 64 * PITCH) * 4)

__global__ void __launch_bounds__(256, 2) qkv_gemm(
    const float* __restrict__ bq, const float* __restrict__ bk,
    const float* __restrict__ bv)
{
    extern __shared__ uint32_t smem_u[];
    uint32_t* Ahi = smem_u;
    uint32_t* Alo = Ahi + 128 * PITCH;
    uint32_t* Bhi = Alo + 128 * PITCH;
    uint32_t* Blo = Bhi + 64 * PITCH;

    const int z = blockIdx.z;
    const int asel = (z == 0) ? 0 : 1;
    const __nv_bfloat16* Ah = g_ahi + (size_t)asel * MROWS * H;
    const __nv_bfloat16* Al = g_alo + (size_t)asel * MROWS * H;
    const __nv_bfloat16* Wh = g_whi + (size_t)z * H * H;
    const __nv_bfloat16* Wl = g_wlo + (size_t)z * H * H;
    const float* bias = (z == 0) ? bq : (z == 1) ? bk : bv;
    float* C = (z == 0) ? g_q : (z == 1) ? g_k : g_v;

    const int m0 = blockIdx.y * 128;
    const int n0 = blockIdx.x * 64;

    const int tid  = threadIdx.x;
    const int lane = tid & 31;
    const int warp = tid >> 5;
    const int wm = warp & 3;
    const int wn = warp >> 2;
    const int l4 = lane & 3;
    const int g8 = lane >> 2;

    float c[2][4][4];
#pragma unroll
    for (int mi = 0; mi < 2; mi++)
#pragma unroll
        for (int ni = 0; ni < 4; ni++)
#pragma unroll
            for (int e = 0; e < 4; e++) c[mi][ni][e] = 0.0f;

    // uint4 = 8 bf16.  Row of A/W = 96 uint4.
    for (int k0 = 0; k0 < H; k0 += 64) {
        const int kq0 = k0 >> 3;                 // uint4 offset within row
        __syncthreads();
#pragma unroll
        for (int it = 0; it < 4; it++) {
            const int fid = tid + it * 256;      // 0..1023
            const int row = fid >> 3;            // 0..127
            const int q   = fid & 7;             // uint4 within chunk
            const size_t gsrc = (size_t)(m0 + row) * 96 + kq0 + q;
            *(uint4*)&Ahi[row * PITCH + q * 4] = ((const uint4*)Ah)[gsrc];
            *(uint4*)&Alo[row * PITCH + q * 4] = ((const uint4*)Al)[gsrc];
        }
#pragma unroll
        for (int it = 0; it < 2; it++) {
            const int fid = tid + it * 256;      // 0..511
            const int row = fid >> 3;            // 0..63
            const int q   = fid & 7;
            const size_t gsrc = (size_t)(n0 + row) * 96 + kq0 + q;
            *(uint4*)&Bhi[row * PITCH + q * 4] = ((const uint4*)Wh)[gsrc];
            *(uint4*)&Blo[row * PITCH + q * 4] = ((const uint4*)Wl)[gsrc];
        }
        __syncthreads();

#pragma unroll
        for (int kk = 0; kk < 4; kk++) {
            const int pb = kk * 8;
            uint32_t bh[4][2], bl[4][2];
#pragma unroll
            for (int ni = 0; ni < 4; ni++) {
                const int n = (wn * 32 + ni * 8 + g8) * PITCH + pb + l4;
                bh[ni][0] = Bhi[n];     bh[ni][1] = Bhi[n + 4];
                bl[ni][0] = Blo[n];     bl[ni][1] = Blo[n + 4];
            }
#pragma unroll
            for (int mi = 0; mi < 2; mi++) {
                const int r0 = (wm * 32 + mi * 16 + g8) * PITCH + pb + l4;
                const int r1 = r0 + 8 * PITCH;
                uint32_t ah[4], al[4];
                ah[0] = Ahi[r0];     ah[1] = Ahi[r1];
                ah[2] = Ahi[r0 + 4]; ah[3] = Ahi[r1 + 4];
                al[0] = Alo[r0];     al[1] = Alo[r1];
                al[2] = Alo[r0 + 4]; al[3] = Alo[r1 + 4];
#pragma unroll
                for (int ni = 0; ni < 4; ni++) {
                    mma_bf16(c[mi][ni], ah, bh[ni]);
                    mma_bf16(c[mi][ni], ah, bl[ni]);
                    mma_bf16(c[mi][ni], al, bh[ni]);
                }
            }
        }
    }

#pragma unroll
    for (int mi = 0; mi < 2; mi++) {
#pragma unroll
        for (int ni = 0; ni < 4; ni++) {
            const int col = n0 + wn * 32 + ni * 8 + l4 * 2;
            const float2 bi = *(const float2*)&bias[col];
            const int row0 = m0 + wm * 32 + mi * 16 + g8;
            float2 v0 = {c[mi][ni][0] + bi.x, c[mi][ni][1] + bi.y};
            float2 v1 = {c[mi][ni][2] + bi.x, c[mi][ni][3] + bi.y};
            *(float2*)&C[(size_t)row0 * H + col]       = v0;
            *(float2*)&C[(size_t)(row0 + 8) * H + col] = v1;
        }
    }
}

// =================================================================================
// Kernel 2a: band rows r in [0, 511).  Only cols {r-1, r} survive the mask.
// =================================================================================
__global__ void __launch_bounds__(256) band_kernel(
    const float* __restrict__ gate, const float* __restrict__ amask,
    float* __restrict__ out, float* __restrict__ scores_out)
{
    const int lane = threadIdx.x & 31;
    const int w    = threadIdx.x >> 5;
    const int r    = blockIdx.x * 8 + w;
    if (r >= PROX - 1) return;
    const int h = blockIdx.y;
    const int b = blockIdx.z;

    const size_t hoff = (size_t)h * DH;
    const float* qp = g_q + ((size_t)(b * S + r)) * H + hoff;
    const float qa = qp[lane];
    const float qb = qp[lane + 32];

    const float* k1 = g_k + ((size_t)(b * S + r)) * H + hoff;
    float d1 = qa * k1[lane] + qb * k1[lane + 32];
    float d0 = 0.0f;
    if (r > 0) {
        const float* k0 = g_k + ((size_t)(b * S + r - 1)) * H + hoff;
        d0 = qa * k0[lane] + qb * k0[lane + 32];
    }
#pragma unroll
    for (int off = 16; off > 0; off >>= 1) {
        d1 += __shfl_xor_sync(0xFFFFFFFFu, d1, off);
        d0 += __shfl_xor_sync(0xFFFFFFFFu, d0, off);
    }

    const float sc1 = d1 * 0.125f * gate[((size_t)b * S + r) * S + r] + amask[b * S + r];
    float sc0 = NEGV;
    if (r > 0)
        sc0 = d0 * 0.125f * gate[((size_t)b * S + r) * S + (r - 1)] + amask[b * S + r - 1];

    float* srow = scores_out + ((size_t)((b * NHEADS + h) * S + r)) * S;
#pragma unroll
    for (int i = 0; i < 8; i++) {
        const int c0 = (lane + i * 32) * 4;
        float4 vv = {NEGV, NEGV, NEGV, NEGV};
        if (r - 1 >= c0 && r - 1 < c0 + 4) ((float*)&vv)[r - 1 - c0] = sc0;
        if (r     >= c0 && r     < c0 + 4) ((float*)&vv)[r - c0]     = sc1;
        *(float4*)(srow + c0) = vv;
    }

    const float m  = fmaxf(sc0, sc1);
    const float e0 = __expf(sc0 - m);
    const float e1 = __expf(sc1 - m);
    const float inv = 1.0f / (e0 + e1);
    const float p0 = e0 * inv, p1 = e1 * inv;

    const float* v1 = g_v + ((size_t)(b * S + r)) * H + hoff;
    const float* v0 = g_v + ((size_t)(b * S + (r > 0 ? r - 1 : 0))) * H + hoff;
    float* orow = out + ((size_t)(b * S + r)) * H + hoff;
    orow[lane]      = p0 * v0[lane]      + p1 * v1[lane];
    orow[lane + 32] = p0 * v0[lane + 32] + p1 * v1[lane + 32];
}

// =================================================================================
// Kernel 2b: row 511 — fully dense. One block per (b,h). grid = 48, block = 256.
// =================================================================================
__global__ void __launch_bounds__(256) row511_kernel(
    const float* __restrict__ gate, const float* __restrict__ amask,
    float* __restrict__ out, float* __restrict__ scores_out)
{
    const int bh = blockIdx.x;
    const int b = bh / NHEADS, h = bh % NHEADS;
    const int r = PROX - 1;
    const int tid = threadIdx.x;
    const int lane = tid & 31, w = tid >> 5;

    __shared__ float p[S];
    __shared__ float qsm[DH];
    __shared__ float red[8];
    __shared__ float osum[4][DH];

    if (tid < DH) qsm[tid] = g_q[((size_t)(b * S + r)) * H + h * DH + tid];
    __syncthreads();

    float sc[4];
    float* srow = scores_out + ((size_t)((b * NHEADS + h) * S + r)) * S;
#pragma unroll
    for (int i = 0; i < 4; i++) {
        const int c = tid + i * 256;
        const float* kp = g_k + ((size_t)(b * S + c)) * H + h * DH;
        float d = 0.0f;
#pragma unroll
        for (int e = 0; e < DH; e++) d += qsm[e] * kp[e];
        sc[i] = d * 0.125f * gate[((size_t)b * S + r) * S + c] + amask[b * S + c];
        p[c] = sc[i];
        srow[c] = sc[i];
    }

    float m = fmaxf(fmaxf(sc[0], sc[1]), fmaxf(sc[2], sc[3]));
#pragma unroll
    for (int off = 16; off > 0; off >>= 1)
        m = fmaxf(m, __shfl_xor_sync(0xFFFFFFFFu, m, off));
    if (lane == 0) red[w] = m;
    __syncthreads();
    if (tid == 0) {
        float mm = red[0];
#pragma unroll
        for (int i = 1; i < 8; i++) mm = fmaxf(mm, red[i]);
        red[0] = mm;
    }
    __syncthreads();
    m = red[0];
    __syncthreads();

    float s = 0.0f;
#pragma unroll
    for (int i = 0; i < 4; i++) {
        const int c = tid + i * 256;
        const float e = __expf(p[c] - m);
        p[c] = e;
        s += e;
    }
#pragma unroll
    for (int off = 16; off > 0; off >>= 1)
        s += __shfl_xor_sync(0xFFFFFFFFu, s, off);
    if (lane == 0) red[w] = s;
    __syncthreads();
    if (tid == 0) {
        float ss = 0.0f;
#pragma unroll
        for (int i = 0; i < 8; i++) ss += red[i];
        red[0] = 1.0f / ss;
    }
    __syncthreads();
    const float inv = red[0];
#pragma unroll
    for (int i = 0; i < 4; i++) p[tid + i * 256] *= inv;
    __syncthreads();

    const int part = tid >> 6, d = tid & 63;
    float acc = 0.0f;
    for (int c = part * 256; c < part * 256 + 256; c++)
        acc += p[c] * g_v[((size_t)(b * S + c)) * H + h * DH + d];
    osum[part][d] = acc;
    __syncthreads();
    if (tid < DH)
        out[((size_t)(b * S + r)) * H + h * DH + tid] =
            osum[0][tid] + osum[1][tid] + osum[2][tid] + osum[3][tid];
}

// =================================================================================
// Kernel 2c: rows 512..1023.  Surviving cols = [Lc, 512).
// =================================================================================
#define C_PS   0
#define C_QT   (32 * 516)
#define C_KV   (32 * 516 + 64 * 36)
#define C_FLOATS (32 * 516 + 64 * 36 + 8704)
#define C_SMEM_BYTES (C_FLOATS * 4)

__global__ void __launch_bounds__(256) blk_kernel(
    const float* __restrict__ gate, const float* __restrict__ amask,
    const int* __restrict__ feat_len,
    float* __restrict__ out, float* __restrict__ scores_out)
{
    extern __shared__ float sm[];
    float* Ps = sm + C_PS;
    float* Qt = sm + C_QT;
    float* KV = sm + C_KV;

    const int qt = blockIdx.x;
    const int h  = blockIdx.y;
    const int b  = blockIdx.z;
    const int q0 = PROX + qt * 32;
    const int tid = threadIdx.x;

    const int flm1 = feat_len[b] - 1;
    int Lc = flm1 < 0 ? 0 : flm1;
    if (Lc > PROX) Lc = PROX;
    const int n = PROX - Lc;

    const size_t srow0 = (size_t)((b * NHEADS + h) * S + q0) * S;

    if (n == 0) {
        const float4 neg4 = {NEGV, NEGV, NEGV, NEGV};
        for (int idx = tid; idx < 32 * 256; idx += 256) {
            const int rr = idx >> 8;
            const int c4 = (idx & 255) * 4;
            *(float4*)(scores_out + srow0 + (size_t)rr * S + c4) = neg4;
        }
        const int part = tid >> 6, d = tid & 63;
        float acc = 0.0f;
        for (int c = part * 256; c < part * 256 + 256; c++)
            acc += g_v[((size_t)(b * S + c)) * H + h * DH + d];
        sm[part * 64 + d] = acc;
        __syncthreads();
        if (tid < DH) {
            const float mv = (sm[tid] + sm[64 + tid] + sm[128 + tid] + sm[192 + tid])
                             * (1.0f / 1024.0f);
            for (int rr = 0; rr < 32; rr++)
                out[((size_t)(b * S + q0 + rr)) * H + h * DH + tid] = mv;
        }
        return;
    }

    const int kt0 = Lc & ~127;

    {
        const float4 neg4 = {NEGV, NEGV, NEGV, NEGV};
        for (int idx = tid; idx < 32 * 128; idx += 256) {
            const int rr = idx >> 7;
            const int c4 = (idx & 127) * 4;
            *(float4*)(scores_out + srow0 + (size_t)rr * S + 512 + c4) = neg4;
        }
        const int nA = kt0 >> 2;
        if (nA > 0) {
            for (int idx = tid; idx < 32 * nA; idx += 256) {
                const int rr = idx / nA;
                const int c4 = (idx % nA) * 4;
                *(float4*)(scores_out + srow0 + (size_t)rr * S + c4) = neg4;
            }
        }
    }

#pragma unroll
    for (int it = 0; it < 2; it++) {
        const int idx = tid + it * 256;
        const int r   = idx >> 4;
        const int d4  = (idx & 15) * 4;
        const float4 v = *(const float4*)&g_q[(size_t)(b * S + q0 + r) * H + h * DH + d4];
        Qt[(d4 + 0) * 36 + r] = v.x;
        Qt[(d4 + 1) * 36 + r] = v.y;
        Qt[(d4 + 2) * 36 + r] = v.z;
        Qt[(d4 + 3) * 36 + r] = v.w;
    }

    const int qg = tid >> 5;
    const int kg = tid & 31;
    const int qr = qg * 4;

    for (int kt = kt0; kt < PROX; kt += 128) {
        __syncthreads();
#pragma unroll
        for (int it = 0; it < 8; it++) {
            const int idx = tid + it * 256;
            const int r   = idx >> 4;
            const int d4  = (idx & 15) * 4;
            const float4 v = *(const float4*)&g_k[(size_t)(b * S + kt + r) * H + h * DH + d4];
            KV[(d4 + 0) * 132 + r] = v.x;
            KV[(d4 + 1) * 132 + r] = v.y;
            KV[(d4 + 2) * 132 + r] = v.z;
            KV[(d4 + 3) * 132 + r] = v.w;
        }
        __syncthreads();

        float acc[4][4];
#pragma unroll
        for (int i = 0; i < 4; i++)
#pragma unroll
            for (int j = 0; j < 4; j++) acc[i][j] = 0.0f;

#pragma unroll 16
        for (int d = 0; d < 64; d++) {
            const float4 a4 = *(const float4*)&Qt[d * 36 + qr];
            const float4 b4 = *(const float4*)&KV[d * 132 + kg * 4];
            const float a[4] = {a4.x, a4.y, a4.z, a4.w};
            const float bb[4] = {b4.x, b4.y, b4.z, b4.w};
#pragma unroll
            for (int i = 0; i < 4; i++)
#pragma unroll
                for (int j = 0; j < 4; j++) acc[i][j] += a[i] * bb[j];
        }

        const int kbase = kt + kg * 4;
        const float4 am = *(const float4*)&amask[b * S + kbase];
        const float amv[4] = {am.x, am.y, am.z, am.w};
#pragma unroll
        for (int i = 0; i < 4; i++) {
            const int qrow = q0 + qr + i;
            const float4 g = *(const float4*)&gate[((size_t)b * S + qrow) * S + kbase];
            const float gg[4] = {g.x, g.y, g.z, g.w};
            float sc[4];
#pragma unroll
            for (int j = 0; j < 4; j++) {
                const int kc = kbase + j;
                const float v = acc[i][j] * 0.125f * gg[j] + amv[j];
                sc[j] = (kc < Lc) ? NEGV : v;
            }
            const float4 s4 = {sc[0], sc[1], sc[2], sc[3]};
            *(float4*)&Ps[(qr + i) * 516 + kbase] = s4;
            *(float4*)(scores_out + srow0 + (size_t)(qr + i) * S + kbase) = s4;
        }
    }
    __syncthreads();

    {
        const int lane = tid & 31;
        const int w    = tid >> 5;
#pragma unroll
        for (int rr = 0; rr < 4; rr++) {
            float* row = Ps + (w * 4 + rr) * 516;
            float m = -3.4e38f;
            for (int c = kt0 + lane; c < PROX; c += 32) m = fmaxf(m, row[c]);
#pragma unroll
            for (int off = 16; off > 0; off >>= 1)
                m = fmaxf(m, __shfl_xor_sync(0xFFFFFFFFu, m, off));
            float ssum = 0.0f;
            for (int c = kt0 + lane; c < PROX; c += 32) {
                const float e = __expf(row[c] - m);
                row[c] = e;
                ssum += e;
            }
#pragma unroll
            for (int off = 16; off > 0; off >>= 1)
                ssum += __shfl_xor_sync(0xFFFFFFFFu, ssum, off);
            const float inv = 1.0f / ssum;
            for (int c = kt0 + lane; c < PROX; c += 32) row[c] *= inv;
        }
    }
    __syncthreads();

    float oacc[4][2];
#pragma unroll
    for (int i = 0; i < 4; i++) { oacc[i][0] = 0.0f; oacc[i][1] = 0.0f; }

    for (int kt = kt0; kt < PROX; kt += 128) {
#pragma unroll
        for (int it = 0; it < 8; it++) {
            const int idx = tid + it * 256;
            const int r   = idx >> 4;
            const int d4  = (idx & 15) * 4;
            *(float4*)&KV[r * 68 + d4] =
                *(const float4*)&g_v[(size_t)(b * S + kt + r) * H + h * DH + d4];
        }
        __syncthreads();

#pragma unroll 2
        for (int k = 0; k < 128; k += 4) {
            float4 pv[4];
#pragma unroll
            for (int i = 0; i < 4; i++)
                pv[i] = *(const float4*)&Ps[(qr + i) * 516 + kt + k];
#pragma unroll
            for (int j = 0; j < 4; j++) {
                const float v0 = KV[(k + j) * 68 + kg];
                const float v1 = KV[(k + j) * 68 + kg + 32];
                const float pj[4] = {
                    j == 0 ? pv[0].x : j == 1 ? pv[0].y : j == 2 ? pv[0].z : pv[0].w,
                    j == 0 ? pv[1].x : j == 1 ? pv[1].y : j == 2 ? pv[1].z : pv[1].w,
                    j == 0 ? pv[2].x : j == 1 ? pv[2].y : j == 2 ? pv[2].z : pv[2].w,
                    j == 0 ? pv[3].x : j == 1 ? pv[3].y : j == 2 ? pv[3].z : pv[3].w };
#pragma unroll
                for (int i = 0; i < 4; i++) {
                    oacc[i][0] += pj[i] * v0;
                    oacc[i][1] += pj[i] * v1;
                }
            }
        }
        __syncthreads();
    }

#pragma unroll
    for (int i = 0; i < 4; i++) {
        const size_t ooff = (size_t)(b * S + q0 + qr + i) * H + h * DH;
        out[ooff + kg]      = oacc[i][0];
        out[ooff + kg + 32] = oacc[i][1];
    }
}

// =================================================================================
extern "C" void kernel_launch(void* const* d_in, const int* in_sizes, int n_in,
                              void* d_out, int out_size) {
    const float* hidden   = (const float*)d_in[0];
    const float* context  = (const float*)d_in[1];
    const float* amask    = (const float*)d_in[2];
    const float* gate     = (const float*)d_in[3];
    const float* vis      = (const float*)d_in[4];
    const float* Wq       = (const float*)d_in[5];
    const float* bq       = (const float*)d_in[6];
    const float* Wk       = (const float*)d_in[7];
    const float* bk       = (const float*)d_in[8];
    const float* Wv       = (const float*)d_in[9];
    const float* bv       = (const float*)d_in[10];
    const int*   feat_len = (const int*)d_in[11];

    float* out_ptr = (float*)d_out;
    float* scores_ptr = out_ptr + (size_t)BATCH * S * H;

    split_inputs<<<dim3(3072, 2), 256>>>(hidden, context, vis, feat_len);
    split_w<<<dim3(576, 3), 256>>>(Wq, Wk, Wv);

    cudaFuncSetAttribute(qkv_gemm, cudaFuncAttributeMaxDynamicSharedMemorySize,
                         G_SMEM_BYTES);
    qkv_gemm<<<dim3(12, 32, 3), 256, G_SMEM_BYTES>>>(bq, bk, bv);

    band_kernel<<<dim3(64, NHEADS, BATCH), 256>>>(gate, amask, out_ptr, scores_ptr);
    row511_kernel<<<dim3(BATCH * NHEADS), 256>>>(gate, amask, out_ptr, scores_ptr);

    cudaFuncSetAttribute(blk_kernel, cudaFuncAttributeMaxDynamicSharedMemorySize,
                         C_SMEM_BYTES);
    blk_kernel<<<dim3(16, NHEADS, BATCH), 256, C_SMEM_BYTES>>>(
        gate, amask, feat_len, out_ptr, scores_ptr);
}